// round 12
// baseline (speedup 1.0000x reference)
#include <cuda_runtime.h>
#include <cuda_fp16.h>
#include <cstdint>

#define Bb 4
#define Hh 16
#define Ss 1024
#define Dd 128
#define BM 64
#define BN 64
#define NT (Ss/BN)
#define THREADS 192
#define NCONS 128
#define TEMP 11.313708498984761f

// ---- smem word offsets (32-bit words) ----
#define OQ16 0                      // Q frag-major fp16: [mb4][kk8][lane32][4w] = 4096 w
#define OK16 4096                   // K fp16 row-major [64][68w] x2 bufs
#define KBUF 4352
#define OV16 12800                  // V fp16 kpair-packed [32][136w] x2 bufs
#define VBUF 4352
#define OS16 21504                  // S fp16 frag-major [mb4][kkv4][lane32][4w] x2 bufs
#define SBUF 2048
#define SMEM_WORDS 25600
#define SMEM_BYTES (SMEM_WORDS*4)   // 102400

__device__ unsigned char g_flags[Bb*16*16];

__device__ __forceinline__ uint32_t hpack(float lo, float hi){
    uint32_t r; asm("cvt.rn.f16x2.f32 %0, %1, %2;" : "=r"(r) : "f"(hi), "f"(lo)); return r;
}
__device__ __forceinline__ void mma16(float* c, uint32_t a0, uint32_t a1, uint32_t a2, uint32_t a3,
                                      uint32_t b0, uint32_t b1){
    asm volatile(
        "mma.sync.aligned.m16n8k16.row.col.f32.f16.f16.f32 "
        "{%0,%1,%2,%3},{%4,%5,%6,%7},{%8,%9},{%0,%1,%2,%3};"
        : "+f"(c[0]), "+f"(c[1]), "+f"(c[2]), "+f"(c[3])
        : "r"(a0), "r"(a1), "r"(a2), "r"(a3), "r"(b0), "r"(b1));
}

extern __shared__ uint32_t sm[];

// ---- pre-pass: per (b, qtile64, ktile64) all-ones mask flag ----
__global__ void mask_flags_kernel(const int* __restrict__ mask){
    const int kt = blockIdx.x, qt = blockIdx.y, b = blockIdx.z;
    const int* mb = mask + ((size_t)b*Ss + (size_t)qt*BM)*Ss + kt*BN;
    int ok = 1;
    #pragma unroll
    for (int i = 0; i < 4; i++) {
        int idx = threadIdx.x + i*256;          // 1024 int4 of [64][64]
        int r = idx >> 4, c = (idx & 15) * 4;
        int4 m = *(const int4*)(mb + (size_t)r*Ss + c);
        ok &= (m.x && m.y && m.z && m.w) ? 1 : 0;
    }
    ok = __syncthreads_and(ok);
    if (threadIdx.x == 0) g_flags[(b*16 + qt)*16 + kt] = (unsigned char)ok;
}

// producer (64 threads): K tile [64][128] fp32 -> fp16 row-major, depth-2 reg pipeline
__device__ __forceinline__ void produce_k(const float* __restrict__ kg, int kbuf, int pt){
    const float4* kp4 = (const float4*)kg;
    uint32_t* sk = sm + OK16 + kbuf*KBUF;
    float4 b0[8], b1[8];
    #pragma unroll
    for (int i = 0; i < 8; i++) b0[i] = kp4[pt + i*64];
    #pragma unroll
    for (int i = 0; i < 8; i++) b1[i] = kp4[pt + (8+i)*64];
    #pragma unroll
    for (int c = 0; c < 4; c++) {
        float4* cur = (c & 1) ? b1 : b0;
        #pragma unroll
        for (int i = 0; i < 8; i++) {
            int idx = pt + (c*8+i)*64;         // [64 r][32 c4]
            int r = idx >> 5, c4 = idx & 31;
            uint2 u = make_uint2(hpack(cur[i].x, cur[i].y), hpack(cur[i].z, cur[i].w));
            *(uint2*)&sk[r*68 + c4*2] = u;
        }
        if (c < 2) {
            #pragma unroll
            for (int i = 0; i < 8; i++) cur[i] = kp4[pt + ((c+2)*8+i)*64];
        }
    }
}

// producer: V tile -> kpair-packed fp16, depth-2 pipeline (4-pair chunks)
__device__ __forceinline__ void produce_v(const float* __restrict__ vg, int vbuf, int pt){
    const float4* vp4 = (const float4*)vg;
    uint32_t* sv = sm + OV16 + vbuf*VBUF;
    float4 a0[4], r0v[4], a1[4], r1v[4];
    #pragma unroll
    for (int i = 0; i < 4; i++) {
        int idx = pt + i*64;
        int kpi = idx >> 5, c4 = idx & 31;
        a0[i]  = vp4[(2*kpi  )*32 + c4];
        r0v[i] = vp4[(2*kpi+1)*32 + c4];
    }
    #pragma unroll
    for (int i = 0; i < 4; i++) {
        int idx = pt + (4+i)*64;
        int kpi = idx >> 5, c4 = idx & 31;
        a1[i]  = vp4[(2*kpi  )*32 + c4];
        r1v[i] = vp4[(2*kpi+1)*32 + c4];
    }
    #pragma unroll
    for (int c = 0; c < 4; c++) {
        float4* ca = (c & 1) ? a1 : a0;
        float4* cr = (c & 1) ? r1v : r0v;
        #pragma unroll
        for (int i = 0; i < 4; i++) {
            int idx = pt + (c*4+i)*64;         // [32 kp][32 c4]
            int kpi = idx >> 5, c4 = idx & 31;
            uint4 u = make_uint4(hpack(ca[i].x, cr[i].x), hpack(ca[i].y, cr[i].y),
                                 hpack(ca[i].z, cr[i].z), hpack(ca[i].w, cr[i].w));
            *(uint4*)&sv[kpi*136 + c4*4] = u;
        }
        if (c < 2) {
            #pragma unroll
            for (int i = 0; i < 4; i++) {
                int idx = pt + ((c+2)*4+i)*64;
                int kpi = idx >> 5, c4 = idx & 31;
                ca[i] = vp4[(2*kpi  )*32 + c4];
                cr[i] = vp4[(2*kpi+1)*32 + c4];
            }
        }
    }
}

__global__ __launch_bounds__(THREADS, 2)
void sdpa_relu15_v9(const float* __restrict__ q, const float* __restrict__ k,
                    const float* __restrict__ v, const int* __restrict__ mask,
                    float* __restrict__ out, float* __restrict__ attn)
{
    const int tid  = threadIdx.x;
    const int lane = tid & 31;
    const int g    = lane >> 2, tg = lane & 3;
    const int bh   = blockIdx.y;
    const int q0   = blockIdx.x * BM;
    const int b    = bh >> 4;
    const size_t mbase = (size_t)b * Ss * Ss;
    const unsigned char* flags = &g_flags[(b*16 + blockIdx.x)*16];

    const float* kb = k + (size_t)bh*Ss*Dd;
    const float* vb = v + (size_t)bh*Ss*Dd;
    float* ag_base = attn + (size_t)bh*Ss*Ss + (size_t)q0*Ss;

    const int w  = tid >> 5;
    const int wm = w & 1, wn = (w >> 1) & 1;   // consumers: 2(m) x 2(n)

    // ---- prologue ----
    if (tid < NCONS) {
        // consumers: Q[64x128] -> frag-major fp16 (scaled)
        const float invT = 1.0f / TEMP;
        const float4* qg = (const float4*)(q + ((size_t)bh*Ss + q0)*Dd);
        #pragma unroll
        for (int i = 0; i < 16; i++) {
            int idx = tid + i*NCONS;           // [64 r][32 c4]
            int r = idx >> 5, c4 = idx & 31;
            float4 t = qg[idx];
            uint32_t p0 = hpack(t.x*invT, t.y*invT);
            uint32_t p1 = hpack(t.z*invT, t.w*invT);
            int mb_ = r >> 4, kk = c4 >> 2;
            int khalf = (c4 & 3) >= 2;
            int tg0 = 2*(c4 & 1);
            int j = ((r >> 3) & 1) + 2*khalf;
            uint32_t wbase = (uint32_t)(((mb_*8 + kk)*32 + (r&7)*4 + tg0)*4 + j);
            sm[OQ16 + wbase]     = p0;
            sm[OQ16 + wbase + 4] = p1;
        }
    } else {
        const int pt = tid - NCONS;            // 0..63
        produce_k(kb, 0, pt);
        produce_k(kb + (size_t)BN*Dd, 1, pt);
        produce_v(vb, 0, pt);
    }
    __syncthreads();

    // consumer lambdas -------------------------------------------------
    auto gemm1_epi = [&](int t){
        const uint32_t* sk = sm + OK16 + (t & 1)*KBUF;
        float sacc[2][4][4];
        #pragma unroll
        for (int mi = 0; mi < 2; mi++)
            #pragma unroll
            for (int ni = 0; ni < 4; ni++)
                { sacc[mi][ni][0]=0.f; sacc[mi][ni][1]=0.f; sacc[mi][ni][2]=0.f; sacc[mi][ni][3]=0.f; }
        #pragma unroll
        for (int kk = 0; kk < 8; kk++) {
            uint4 aa0 = *(const uint4*)&sm[OQ16 + ((2*wm  )*8 + kk)*128 + lane*4];
            uint4 aa1 = *(const uint4*)&sm[OQ16 + ((2*wm+1)*8 + kk)*128 + lane*4];
            #pragma unroll
            for (int ni = 0; ni < 4; ni++) {
                int n = wn*32 + ni*8 + g;
                uint32_t b0 = sk[n*68 + kk*8 + tg];
                uint32_t b1 = sk[n*68 + kk*8 + tg + 4];
                mma16(sacc[0][ni], aa0.x, aa0.y, aa0.z, aa0.w, b0, b1);
                mma16(sacc[1][ni], aa1.x, aa1.y, aa1.z, aa1.w, b0, b1);
            }
        }
        const int n0 = t * BN;
        const unsigned char fl = flags[t];
        uint32_t* s16 = sm + OS16 + (t & 1)*SBUF;
        #pragma unroll
        for (int mi = 0; mi < 2; mi++) {
            const int r = wm*32 + mi*16 + g;
            const int mb_w = wm*2 + mi;
            #pragma unroll
            for (int ni = 0; ni < 4; ni++) {
                const int cc = wn*32 + ni*8 + 2*tg;
                float* s4 = sacc[mi][ni];
                float v0 = s4[0], v1 = s4[1], v2 = s4[2], v3 = s4[3];
                if (!fl) {
                    const int* mrow = mask + mbase + (size_t)(q0+r)*Ss + n0 + cc;
                    int2 m0 = *(const int2*)mrow;
                    int2 m1 = *(const int2*)(mrow + 8*Ss);
                    if (!m0.x) v0 = 0.f; if (!m0.y) v1 = 0.f;
                    if (!m1.x) v2 = 0.f; if (!m1.y) v3 = 0.f;
                }
                v0 = fminf(fmaxf(v0,0.f),15.f); v1 = fminf(fmaxf(v1,0.f),15.f);
                v2 = fminf(fmaxf(v2,0.f),15.f); v3 = fminf(fmaxf(v3,0.f),15.f);
                const int kkv = wn*2 + (ni >> 1);
                uint32_t wadr = (uint32_t)(((mb_w*4 + kkv)*32 + g*4 + tg)*4 + (ni&1)*2);
                *(uint2*)&s16[wadr] = make_uint2(hpack(v0, v1), hpack(v2, v3));
            }
        }
    };

    float o[2][8][4];
    #pragma unroll
    for (int mi = 0; mi < 2; mi++)
        #pragma unroll
        for (int di = 0; di < 8; di++)
            { o[mi][di][0]=0.f; o[mi][di][1]=0.f; o[mi][di][2]=0.f; o[mi][di][3]=0.f; }

    auto gemm2 = [&](int t){
        const uint32_t* sv  = sm + OV16 + (t & 1)*VBUF;
        const uint32_t* s16 = sm + OS16 + (t & 1)*SBUF;
        #pragma unroll
        for (int kkv = 0; kkv < 4; kkv++) {
            uint4 a0v = *(const uint4*)&s16[((wm*2  )*4 + kkv)*128 + lane*4];
            uint4 a1v = *(const uint4*)&s16[((wm*2+1)*4 + kkv)*128 + lane*4];
            #pragma unroll
            for (int di = 0; di < 8; di++) {
                int n = wn*64 + di*8 + g;
                uint32_t b0 = sv[(kkv*8 + tg    )*136 + n];
                uint32_t b1 = sv[(kkv*8 + tg + 4)*136 + n];
                mma16(o[0][di], a0v.x, a0v.y, a0v.z, a0v.w, b0, b1);
                mma16(o[1][di], a1v.x, a1v.y, a1v.z, a1v.w, b0, b1);
            }
        }
    };

    // ---- pre-phase: S(0) ----
    if (tid < NCONS) gemm1_epi(0);
    __syncthreads();

    // ---- main pipeline: ONE barrier per phase ----
    for (int nt = 0; nt < NT; nt++) {
        if (tid < NCONS) {
            if (nt < NT-1) gemm1_epi(nt+1);
            gemm2(nt);
        } else {
            const int pt = tid - NCONS;        // 0..63
            const int pw = pt >> 5;            // producer warp 0..1
            const int ln = tid & 31;
            if (nt < NT-2) produce_k(kb + (size_t)(nt+2)*BN*Dd, (nt+2) & 1, pt);
            if (nt < NT-1) produce_v(vb + (size_t)(nt+1)*BN*Dd, (nt+1) & 1, pt);
            // stream attn(nt) from S16 buf nt&1 (h2f exact)
            {
                float* ag = ag_base + nt*BN;
                const uint32_t* s16 = sm + OS16 + (nt & 1)*SBUF;
                const int g_ = ln >> 2, tg_ = ln & 3;
                #pragma unroll
                for (int i = 0; i < 8; i++) {
                    int chunk = pw*8 + i;          // mb = chunk>>2, kkv = chunk&3
                    uint4 u = *(const uint4*)&s16[chunk*128 + ln*4];
                    int r0 = (chunk >> 2)*16 + g_;
                    int c  = (chunk & 3)*16 + 2*tg_;
                    float* arow = ag + (size_t)r0*Ss + c;
                    float2 f;
                    f = __half22float2(*(__half2*)&u.x); *(float2*)(arow)            = f;
                    f = __half22float2(*(__half2*)&u.y); *(float2*)(arow + 8*Ss)     = f;
                    f = __half22float2(*(__half2*)&u.z); *(float2*)(arow + 8)        = f;
                    f = __half22float2(*(__half2*)&u.w); *(float2*)(arow + 8*Ss + 8) = f;
                }
            }
        }
        __syncthreads();
    }

    // ---- O writeout: direct STG.64 from accumulators (full 32B sectors) ----
    if (tid < NCONS) {
        float* og = out + ((size_t)bh*Ss + q0) * Dd;
        #pragma unroll
        for (int mi = 0; mi < 2; mi++) {
            const int r = wm*32 + mi*16 + g;
            #pragma unroll
            for (int di = 0; di < 8; di++) {
                const int c = wn*64 + di*8 + 2*tg;
                float* orow = og + (size_t)r*Dd + c;
                *(float2*)orow          = make_float2(o[mi][di][0], o[mi][di][1]);
                *(float2*)(orow + 8*Dd) = make_float2(o[mi][di][2], o[mi][di][3]);
            }
        }
    }
}

extern "C" void kernel_launch(void* const* d_in, const int* in_sizes, int n_in,
                              void* d_out, int out_size)
{
    const float* q    = (const float*)d_in[0];
    const float* k    = (const float*)d_in[1];
    const float* v    = (const float*)d_in[2];
    const int*   mask = (const int*)  d_in[3];
    float* out  = (float*)d_out;
    float* attn = out + (size_t)Bb*Hh*Ss*Dd;

    mask_flags_kernel<<<dim3(16, 16, Bb), 256>>>(mask);

    cudaFuncSetAttribute(sdpa_relu15_v9,
                         cudaFuncAttributeMaxDynamicSharedMemorySize, SMEM_BYTES);
    dim3 grid(Ss/BM, Bb*Hh);
    sdpa_relu15_v9<<<grid, THREADS, SMEM_BYTES>>>(q, k, v, mask, out, attn);
}

// round 13
// speedup vs baseline: 1.3289x; 1.3289x over previous
#include <cuda_runtime.h>
#include <cuda_fp16.h>
#include <cstdint>

#define Bb 4
#define Hh 16
#define Ss 1024
#define Dd 128
#define BM 128
#define BN 64
#define NT (Ss/BN)
#define THREADS 384
#define NCONS 256
#define TEMP 11.313708498984761f

// ---- smem word offsets (32-bit words) ----
#define OQ16 0                      // Q frag-major fp16: [mb8][kk8][lane32][4w] = 8192 w
#define OK16 8192                   // K fp16 row-major [64][68w] x2 bufs
#define KBUF 4352
#define OV16 16896                  // V fp16 kpair-packed [32][136w] x3 bufs
#define VBUF 4352
#define OS16 29952                  // S fp16 frag-major [mb8][kkv4][lane32][4w] x2 bufs
#define SBUF 4096
#define SMEM_WORDS 38144
#define SMEM_BYTES (SMEM_WORDS*4)   // 152576

__device__ unsigned char g_flags[Bb*8*16];

__device__ __forceinline__ uint32_t hpack(float lo, float hi){
    uint32_t r; asm("cvt.rn.f16x2.f32 %0, %1, %2;" : "=r"(r) : "f"(hi), "f"(lo)); return r;
}
__device__ __forceinline__ void mma16(float* c, uint32_t a0, uint32_t a1, uint32_t a2, uint32_t a3,
                                      uint32_t b0, uint32_t b1){
    asm volatile(
        "mma.sync.aligned.m16n8k16.row.col.f32.f16.f16.f32 "
        "{%0,%1,%2,%3},{%4,%5,%6,%7},{%8,%9},{%0,%1,%2,%3};"
        : "+f"(c[0]), "+f"(c[1]), "+f"(c[2]), "+f"(c[3])
        : "r"(a0), "r"(a1), "r"(a2), "r"(a3), "r"(b0), "r"(b1));
}

extern __shared__ uint32_t sm[];

// ---- pre-pass: per (b, qtile128, ktile64) all-ones mask flag ----
__global__ void mask_flags_kernel(const int* __restrict__ mask){
    const int kt = blockIdx.x, qt = blockIdx.y, b = blockIdx.z;
    const int* mb = mask + ((size_t)b*Ss + (size_t)qt*BM)*Ss + kt*BN;
    int ok = 1;
    #pragma unroll
    for (int i = 0; i < 8; i++) {
        int idx = threadIdx.x + i*256;
        int r = idx >> 4, c = (idx & 15) * 4;
        int4 m = *(const int4*)(mb + (size_t)r*Ss + c);
        ok &= (m.x && m.y && m.z && m.w) ? 1 : 0;
    }
    ok = __syncthreads_and(ok);
    if (threadIdx.x == 0) g_flags[(b*8 + qt)*16 + kt] = (unsigned char)ok;
}

// producer: load K/V tile (row-major fp32 [64][128]) -> fp16 smem buffers
__device__ __forceinline__ void produce_kv(const float* __restrict__ kg,
                                           const float* __restrict__ vg,
                                           int kbuf, int vbuf, int pt)
{
    const float4* kp4 = (const float4*)kg;
    const float4* vp4 = (const float4*)vg;
    float4 va[8], vbr[8], ka[16];
    #pragma unroll
    for (int i = 0; i < 8; i++) {
        int idx = pt + i*128;              // [32 kp][32 c4]
        int kpi = idx >> 5, c4 = idx & 31;
        va[i]  = vp4[(2*kpi  )*32 + c4];
        vbr[i] = vp4[(2*kpi+1)*32 + c4];
    }
    #pragma unroll
    for (int i = 0; i < 16; i++) {
        int idx = pt + i*128;              // [64 r][32 c4]
        int r = idx >> 5, c4 = idx & 31;
        ka[i] = kp4[r*32 + c4];
    }
    uint32_t* sv = sm + OV16 + vbuf*VBUF;
    #pragma unroll
    for (int i = 0; i < 8; i++) {
        int idx = pt + i*128;
        int kpi = idx >> 5, c4 = idx & 31;
        uint4 u = make_uint4(hpack(va[i].x, vbr[i].x), hpack(va[i].y, vbr[i].y),
                             hpack(va[i].z, vbr[i].z), hpack(va[i].w, vbr[i].w));
        *(uint4*)&sv[kpi*136 + c4*4] = u;
    }
    uint32_t* sk = sm + OK16 + kbuf*KBUF;
    #pragma unroll
    for (int i = 0; i < 16; i++) {
        int idx = pt + i*128;
        int r = idx >> 5, c4 = idx & 31;
        uint2 u = make_uint2(hpack(ka[i].x, ka[i].y), hpack(ka[i].z, ka[i].w));
        *(uint2*)&sk[r*68 + c4*2] = u;
    }
}

__global__ __launch_bounds__(THREADS, 1)
void sdpa_relu15_v10(const float* __restrict__ q, const float* __restrict__ k,
                     const float* __restrict__ v, const int* __restrict__ mask,
                     float* __restrict__ out, float* __restrict__ attn)
{
    const int tid  = threadIdx.x;
    const int lane = tid & 31;
    const int g    = lane >> 2, tg = lane & 3;
    const int bh   = blockIdx.y;
    const int q0   = blockIdx.x * BM;
    const int b    = bh >> 4;
    const size_t mbase = (size_t)b * Ss * Ss;
    const unsigned char* flags = &g_flags[(b*8 + blockIdx.x)*16];

    const float* kb = k + (size_t)bh*Ss*Dd;
    const float* vb = v + (size_t)bh*Ss*Dd;
    float* ag_base = attn + (size_t)bh*Ss*Ss + (size_t)q0*Ss;

    const int w  = tid >> 5;
    const int wm = w & 3, wn = (w >> 2) & 1;   // consumers: 4(m) x 2(n)

    // ---- prologue ----
    if (tid < NCONS) {
        // consumers: Q -> frag-major fp16 (scaled)
        const float invT = 1.0f / TEMP;
        const float4* qg = (const float4*)(q + ((size_t)bh*Ss + q0)*Dd);
        #pragma unroll
        for (int i = 0; i < 16; i++) {
            int idx = tid + i*NCONS;           // [128 r][32 c4]
            int r = idx >> 5, c4 = idx & 31;
            float4 t = qg[idx];
            uint32_t p0 = hpack(t.x*invT, t.y*invT);
            uint32_t p1 = hpack(t.z*invT, t.w*invT);
            int mb_ = r >> 4, kk = c4 >> 2;
            int khalf = (c4 & 3) >= 2;
            int tg0 = 2*(c4 & 1);
            int j = ((r >> 3) & 1) + 2*khalf;
            uint32_t wbase = (uint32_t)(((mb_*8 + kk)*32 + (r&7)*4 + tg0)*4 + j);
            sm[OQ16 + wbase]     = p0;
            sm[OQ16 + wbase + 4] = p1;
        }
    } else {
        // producers: tiles 0 and 1 (2-tile lead)
        produce_kv(kb, vb, 0, 0, tid - NCONS);
        produce_kv(kb + (size_t)BN*Dd, vb + (size_t)BN*Dd, 1, 1, tid - NCONS);
    }
    __syncthreads();

    float o[2][8][4];
    #pragma unroll
    for (int mi = 0; mi < 2; mi++)
        #pragma unroll
        for (int di = 0; di < 8; di++)
            { o[mi][di][0]=0.f; o[mi][di][1]=0.f; o[mi][di][2]=0.f; o[mi][di][3]=0.f; }

    // epilogue helper: mask+clip sacc -> S16 buf (t&1)
    auto epi = [&](int t, float sacc[2][4][4]){
        const int n0 = t * BN;
        const unsigned char fl = flags[t];
        uint32_t* s16 = sm + OS16 + (t & 1)*SBUF;
        #pragma unroll
        for (int mi = 0; mi < 2; mi++) {
            const int r = wm*32 + mi*16 + g;
            const int mb_w = wm*2 + mi;
            #pragma unroll
            for (int ni = 0; ni < 4; ni++) {
                const int cc = wn*32 + ni*8 + 2*tg;
                float* s4 = sacc[mi][ni];
                float v0 = s4[0], v1 = s4[1], v2 = s4[2], v3 = s4[3];
                if (!fl) {
                    const int* mrow = mask + mbase + (size_t)(q0+r)*Ss + n0 + cc;
                    int2 m0 = *(const int2*)mrow;
                    int2 m1 = *(const int2*)(mrow + 8*Ss);
                    if (!m0.x) v0 = 0.f; if (!m0.y) v1 = 0.f;
                    if (!m1.x) v2 = 0.f; if (!m1.y) v3 = 0.f;
                }
                v0 = fminf(fmaxf(v0,0.f),15.f); v1 = fminf(fmaxf(v1,0.f),15.f);
                v2 = fminf(fmaxf(v2,0.f),15.f); v3 = fminf(fmaxf(v3,0.f),15.f);
                const int kkv = wn*2 + (ni >> 1);
                uint32_t wadr = (uint32_t)(((mb_w*4 + kkv)*32 + g*4 + tg)*4 + (ni&1)*2);
                *(uint2*)&s16[wadr] = make_uint2(hpack(v0, v1), hpack(v2, v3));
            }
        }
    };

    // one GEMM2 kkv-step (16 MMAs) for tile tv
    auto gemm2_step = [&](int tv, int kkv){
        const uint32_t* sv  = sm + OV16 + (tv % 3)*VBUF;
        const uint32_t* s16 = sm + OS16 + (tv & 1)*SBUF;
        uint4 a0v = *(const uint4*)&s16[((wm*2  )*4 + kkv)*128 + lane*4];
        uint4 a1v = *(const uint4*)&s16[((wm*2+1)*4 + kkv)*128 + lane*4];
        #pragma unroll
        for (int di = 0; di < 8; di++) {
            int n = wn*64 + di*8 + g;
            uint32_t b0 = sv[(kkv*8 + tg    )*136 + n];
            uint32_t b1 = sv[(kkv*8 + tg + 4)*136 + n];
            mma16(o[0][di], a0v.x, a0v.y, a0v.z, a0v.w, b0, b1);
            mma16(o[1][di], a1v.x, a1v.y, a1v.z, a1v.w, b0, b1);
        }
    };

    // fused steady-state phase: GEMM1(tq) interleaved with GEMM2(tv), then epi(tq)
    auto fused_phase = [&](int tq, int tv){
        const uint32_t* sk = sm + OK16 + (tq & 1)*KBUF;
        float sacc[2][4][4];
        #pragma unroll
        for (int mi = 0; mi < 2; mi++)
            #pragma unroll
            for (int ni = 0; ni < 4; ni++)
                { sacc[mi][ni][0]=0.f; sacc[mi][ni][1]=0.f; sacc[mi][ni][2]=0.f; sacc[mi][ni][3]=0.f; }
        #pragma unroll
        for (int kk = 0; kk < 8; kk++) {
            uint4 aa0 = *(const uint4*)&sm[OQ16 + ((2*wm  )*8 + kk)*128 + lane*4];
            uint4 aa1 = *(const uint4*)&sm[OQ16 + ((2*wm+1)*8 + kk)*128 + lane*4];
            #pragma unroll
            for (int ni = 0; ni < 4; ni++) {
                int n = wn*32 + ni*8 + g;
                uint32_t b0 = sk[n*68 + kk*8 + tg];
                uint32_t b1 = sk[n*68 + kk*8 + tg + 4];
                mma16(sacc[0][ni], aa0.x, aa0.y, aa0.z, aa0.w, b0, b1);
                mma16(sacc[1][ni], aa1.x, aa1.y, aa1.z, aa1.w, b0, b1);
            }
            if (kk & 1) gemm2_step(tv, kk >> 1);   // interleaved independent stream
        }
        epi(tq, sacc);
    };

    // plain GEMM1+epi (used for tile 0 pre-phase)
    auto gemm1_epi = [&](int t){
        const uint32_t* sk = sm + OK16 + (t & 1)*KBUF;
        float sacc[2][4][4];
        #pragma unroll
        for (int mi = 0; mi < 2; mi++)
            #pragma unroll
            for (int ni = 0; ni < 4; ni++)
                { sacc[mi][ni][0]=0.f; sacc[mi][ni][1]=0.f; sacc[mi][ni][2]=0.f; sacc[mi][ni][3]=0.f; }
        #pragma unroll
        for (int kk = 0; kk < 8; kk++) {
            uint4 aa0 = *(const uint4*)&sm[OQ16 + ((2*wm  )*8 + kk)*128 + lane*4];
            uint4 aa1 = *(const uint4*)&sm[OQ16 + ((2*wm+1)*8 + kk)*128 + lane*4];
            #pragma unroll
            for (int ni = 0; ni < 4; ni++) {
                int n = wn*32 + ni*8 + g;
                uint32_t b0 = sk[n*68 + kk*8 + tg];
                uint32_t b1 = sk[n*68 + kk*8 + tg + 4];
                mma16(sacc[0][ni], aa0.x, aa0.y, aa0.z, aa0.w, b0, b1);
                mma16(sacc[1][ni], aa1.x, aa1.y, aa1.z, aa1.w, b0, b1);
            }
        }
        epi(t, sacc);
    };

    // ---- pre-phase: S(0) ----
    if (tid < NCONS) gemm1_epi(0);
    __syncthreads();

    // ---- main pipeline: ONE barrier per phase ----
    for (int nt = 0; nt < NT; nt++) {
        if (tid < NCONS) {
            if (nt < NT-1) {
                fused_phase(nt+1, nt);             // GEMM1(nt+1) ⊕ GEMM2(nt)
            } else {
                #pragma unroll
                for (int kkv = 0; kkv < 4; kkv++) gemm2_step(nt, kkv);
            }
        } else {
            const int pt = tid - NCONS;        // 0..127
            const int pw = pt >> 5;
            const int ln = tid & 31;
            if (nt < NT-2)
                produce_kv(kb + (size_t)(nt+2)*BN*Dd, vb + (size_t)(nt+2)*BN*Dd,
                           (nt+2) & 1, (nt+2) % 3, pt);
            // stream attn(nt) from S16 buf nt&1 (h2f exact)
            {
                float* ag = ag_base + nt*BN;
                const uint32_t* s16 = sm + OS16 + (nt & 1)*SBUF;
                const int g_ = ln >> 2, tg_ = ln & 3;
                #pragma unroll
                for (int i = 0; i < 8; i++) {
                    int chunk = pw*8 + i;          // mb = chunk>>2, kkv = chunk&3
                    uint4 u = *(const uint4*)&s16[chunk*128 + ln*4];
                    int r0 = (chunk >> 2)*16 + g_;
                    int c  = (chunk & 3)*16 + 2*tg_;
                    float* arow = ag + (size_t)r0*Ss + c;
                    float2 f;
                    f = __half22float2(*(__half2*)&u.x); *(float2*)(arow)            = f;
                    f = __half22float2(*(__half2*)&u.y); *(float2*)(arow + 8*Ss)     = f;
                    f = __half22float2(*(__half2*)&u.z); *(float2*)(arow + 8)        = f;
                    f = __half22float2(*(__half2*)&u.w); *(float2*)(arow + 8*Ss + 8) = f;
                }
            }
        }
        __syncthreads();
    }

    // ---- O writeout: direct STG.64 from accumulators (full 32B sectors) ----
    if (tid < NCONS) {
        float* og = out + ((size_t)bh*Ss + q0) * Dd;
        #pragma unroll
        for (int mi = 0; mi < 2; mi++) {
            const int r = wm*32 + mi*16 + g;
            #pragma unroll
            for (int di = 0; di < 8; di++) {
                const int c = wn*64 + di*8 + 2*tg;
                float* orow = og + (size_t)r*Dd + c;
                *(float2*)orow          = make_float2(o[mi][di][0], o[mi][di][1]);
                *(float2*)(orow + 8*Dd) = make_float2(o[mi][di][2], o[mi][di][3]);
            }
        }
    }
}

extern "C" void kernel_launch(void* const* d_in, const int* in_sizes, int n_in,
                              void* d_out, int out_size)
{
    const float* q    = (const float*)d_in[0];
    const float* k    = (const float*)d_in[1];
    const float* v    = (const float*)d_in[2];
    const int*   mask = (const int*)  d_in[3];
    float* out  = (float*)d_out;
    float* attn = out + (size_t)Bb*Hh*Ss*Dd;

    mask_flags_kernel<<<dim3(16, 8, Bb), 256>>>(mask);

    cudaFuncSetAttribute(sdpa_relu15_v10,
                         cudaFuncAttributeMaxDynamicSharedMemorySize, SMEM_BYTES);
    dim3 grid(Ss/BM, Bb*Hh);
    sdpa_relu15_v10<<<grid, THREADS, SMEM_BYTES>>>(q, k, v, mask, out, attn);
}